// round 7
// baseline (speedup 1.0000x reference)
#include <cuda_runtime.h>
#include <cuda_bf16.h>

// Path signature, truncation level 4.
// path: (B=128, S=512, D=8) fp32 -> out: (B, 8+64+512+4096 = 4680) fp32
//
// One CTA per batch, 1024 threads. Time is split into FOUR quarters of 128
// steps (511 real steps + 1 zero pad = identity):
//   group g2 = tid>>9 handles quarters {2g2, 2g2+1}, packed into the two
//   lanes of f32x2 registers (lo = earlier quarter, hi = later quarter).
// Thread m = tid&511 owns (i,j,k) = (m>>6,(m>>3)&7,m&7).
// Combine: stage 1 (per group, lo (x) hi -> half-signature), stage 2
// (half0 (x) half1 across groups through shared memory).

#define SD 512
#define DD 8
#define QT 128                  // steps per quarter (= pair-steps per group)
#define TRP_ROW 260             // padded floats per d-row of transposed table
#define OUT_PER_B (DD + DD*DD + DD*DD*DD + DD*DD*DD*DD)  // 4680

typedef unsigned long long u64;

__device__ __forceinline__ u64 dup2(float x) {
    u64 r; asm("mov.b64 %0, {%1, %1};" : "=l"(r) : "f"(x)); return r;
}
__device__ __forceinline__ u64 fmul2(u64 a, u64 b) {
    u64 r; asm("mul.rn.f32x2 %0, %1, %2;" : "=l"(r) : "l"(a), "l"(b)); return r;
}
__device__ __forceinline__ u64 fadd2(u64 a, u64 b) {
    u64 r; asm("add.rn.f32x2 %0, %1, %2;" : "=l"(r) : "l"(a), "l"(b)); return r;
}
__device__ __forceinline__ u64 ffma2(u64 a, u64 b, u64 c) {
    u64 r; asm("fma.rn.f32x2 %0, %1, %2, %3;" : "=l"(r) : "l"(a), "l"(b), "l"(c)); return r;
}
__device__ __forceinline__ void facc2(u64& d, u64 a, u64 b) {
    asm("fma.rn.f32x2 %0, %1, %2, %0;" : "+l"(d) : "l"(a), "l"(b));
}
__device__ __forceinline__ float lo2(u64 a) {
    float l, h; asm("mov.b64 {%0, %1}, %2;" : "=f"(l), "=f"(h) : "l"(a)); return l;
}
__device__ __forceinline__ float hi2(u64 a) {
    float l, h; asm("mov.b64 {%0, %1}, %2;" : "=f"(l), "=f"(h) : "l"(a)); return h;
}

__global__ __launch_bounds__(1024, 1)
void signature_kernel(const float* __restrict__ path, float* __restrict__ out)
{
    // [0 .. 4096)                rowp: 2 groups x 128 tp x 8 dims x float2
    // [4096 .. 4096+16*260)      trp:  2 groups x 8 dims x 128 tp x float2 (padded)
    // combine reuses [0 .. 9360): two 4680-float buffer sets (g2*4680)
    __shared__ __align__(16) float sm[9360];

    const int b   = blockIdx.x;
    const int tid = threadIdx.x;
    const int g2  = tid >> 9;            // time-half group (0 or 1)
    const int m   = tid & 511;
    const float* p = path + (size_t)b * SD * DD;

    // ---- Build pair-interleaved increment tables. Thread t (<512) does inc[t].
    if (tid < 512) {
        const int t = tid;
        float r[8];
        if (t < SD - 1) {
            const float4 a0 = *(const float4*)(p + t * DD);
            const float4 a1 = *(const float4*)(p + t * DD + 4);
            const float4 c0 = *(const float4*)(p + (t + 1) * DD);
            const float4 c1 = *(const float4*)(p + (t + 1) * DD + 4);
            r[0]=c0.x-a0.x; r[1]=c0.y-a0.y; r[2]=c0.z-a0.z; r[3]=c0.w-a0.w;
            r[4]=c1.x-a1.x; r[5]=c1.y-a1.y; r[6]=c1.z-a1.z; r[7]=c1.w-a1.w;
        } else {
            #pragma unroll
            for (int d = 0; d < 8; ++d) r[d] = 0.f;   // pad: exp(0)=identity
        }
        const int q   = t >> 7;          // quarter 0..3
        const int tp  = t & (QT - 1);    // time within quarter
        const int gq  = q >> 1;          // group
        const int sl  = q & 1;           // lane slot: 0 = lo, 1 = hi
        #pragma unroll
        for (int l = 0; l < 8; ++l)
            sm[gq * 2048 + tp * 16 + l * 2 + sl] = r[l];
        #pragma unroll
        for (int d = 0; d < 8; ++d)
            sm[4096 + (gq * 8 + d) * TRP_ROW + tp * 2 + sl] = r[d];
    }
    __syncthreads();

    const int i = m >> 6;
    const int j = (m >> 3) & 7;
    const int k = m & 7;

    u64 s1 = 0ull, s2 = 0ull, s3 = 0ull;
    u64 s4[8];
    #pragma unroll
    for (int l = 0; l < 8; ++l) s4[l] = 0ull;

    const u64 C24 = dup2(1.f / 24.f);
    const u64 C6  = dup2(1.f / 6.f);
    const u64 CH  = dup2(0.5f);
    const u64 C3  = dup2(3.f);

    const float* __restrict__ rowb = sm + g2 * 2048;
    const float* __restrict__ pI = sm + 4096 + (g2 * 8 + i) * TRP_ROW;
    const float* __restrict__ pJ = sm + 4096 + (g2 * 8 + j) * TRP_ROW;
    const float* __restrict__ pK = sm + 4096 + (g2 * 8 + k) * TRP_ROW;

#define STEP(DI, DJ, DK, TP_) do {                                            \
    const ulonglong2 ra = *(const ulonglong2*)(rowb + (TP_) * 16);            \
    const ulonglong2 rb = *(const ulonglong2*)(rowb + (TP_) * 16 + 4);        \
    const ulonglong2 rc = *(const ulonglong2*)(rowb + (TP_) * 16 + 8);        \
    const ulonglong2 rd = *(const ulonglong2*)(rowb + (TP_) * 16 + 12);       \
    const u64 h  = fmul2((DJ), (DK));                                         \
    const u64 t1 = fmul2((DI), C24);                                          \
    const u64 t2 = ffma2(s1, C6, t1);                                         \
    const u64 c0 = ffma2(h, t2, s3);                                          \
    const u64 u  = fmul2(s2, (DK));                                           \
    const u64 c  = ffma2(u, CH, c0);                                          \
    facc2(s4[0], ra.x, c);                                                    \
    facc2(s4[1], ra.y, c);                                                    \
    facc2(s4[2], rb.x, c);                                                    \
    facc2(s4[3], rb.y, c);                                                    \
    facc2(s4[4], rc.x, c);                                                    \
    facc2(s4[5], rc.y, c);                                                    \
    facc2(s4[6], rd.x, c);                                                    \
    facc2(s4[7], rd.y, c);                                                    \
    const u64 g3 = ffma2(t2, C3, t1);   /* = s1/2 + dxi/6 */                  \
    s3 = ffma2(h, g3, fadd2(s3, u));                                          \
    s2 = ffma2((DJ), ffma2((DI), CH, s1), s2);                                \
    s1 = fadd2(s1, (DI));                                                     \
} while (0)

    #pragma unroll 1
    for (int g = 0; g < QT / 2; ++g) {
        // one LDS.128 per stream serves two pair-steps
        const ulonglong2 di = *(const ulonglong2*)(pI + g * 4);
        const ulonglong2 dj = *(const ulonglong2*)(pJ + g * 4);
        const ulonglong2 dk = *(const ulonglong2*)(pK + g * 4);
        STEP(di.x, dj.x, dk.x, 2 * g);
        STEP(di.y, dj.y, dk.y, 2 * g + 1);
    }
#undef STEP

    // ---- Split packed state: A = lo lane (earlier quarter), B = hi lane.
    float a4[8], q4[8];
    #pragma unroll
    for (int l = 0; l < 8; ++l) { a4[l] = lo2(s4[l]); q4[l] = hi2(s4[l]); }
    const float a1 = lo2(s1), a2 = lo2(s2), a3 = lo2(s3);
    const float qb1 = hi2(s1), qb2 = hi2(s2), qb3 = hi2(s3);

    // ================= Stage 1: per-group combine (lo (x) hi) =============
    // Group-local buffers (alias the dead increment tables).
    float* bb = sm + g2 * 4680;
    float* b4 = bb;            // 4096
    float* b3 = bb + 4096;     // 512
    float* b2 = bb + 4608;     // 64
    float* b1 = bb + 4672;     // 8

    __syncthreads();           // everyone done with the increment tables

    *(float4*)(b4 + m * 8)     = make_float4(q4[0], q4[1], q4[2], q4[3]);
    *(float4*)(b4 + m * 8 + 4) = make_float4(q4[4], q4[5], q4[6], q4[7]);
    b3[m] = qb3;
    if (k == 0)        b2[m >> 3] = qb2;
    if ((m & 63) == 0) b1[i]      = qb1;
    __syncthreads();

    float h4[8], h3, h2v, h1v;
    {
        float bb1[8];
        #pragma unroll
        for (int l = 0; l < 8; ++l) bb1[l] = b1[l];
        const float4 u0 = *(const float4*)(b2 + k * 8);
        const float4 u1 = *(const float4*)(b2 + k * 8 + 4);
        const float b2kl[8] = {u0.x,u0.y,u0.z,u0.w,u1.x,u1.y,u1.z,u1.w};
        const float b2jk = b2[j * 8 + k];
        const float4 r0 = *(const float4*)(b3 + j * 64 + k * 8);
        const float4 r1 = *(const float4*)(b3 + j * 64 + k * 8 + 4);
        const float b3jkl[8] = {r0.x,r0.y,r0.z,r0.w,r1.x,r1.y,r1.z,r1.w};
        const float4 w0 = *(const float4*)(b4 + m * 8);
        const float4 w1 = *(const float4*)(b4 + m * 8 + 4);
        const float b4m[8] = {w0.x,w0.y,w0.z,w0.w,w1.x,w1.y,w1.z,w1.w};
        const float bb3m = b3[m];

        #pragma unroll
        for (int l = 0; l < 8; ++l) {
            float acc = a4[l] + b4m[l];
            acc = fmaf(a3, bb1[l],   acc);
            acc = fmaf(a2, b2kl[l],  acc);
            acc = fmaf(a1, b3jkl[l], acc);
            h4[l] = acc;
        }
        h3 = a3 + bb3m;
        h3 = fmaf(a2, bb1[k], h3);
        h3 = fmaf(a1, b2jk,  h3);
        h2v = a2 + b2[m >> 3];
        h2v = fmaf(a1, bb1[j], h2v);
        h1v = a1 + bb1[i];
    }

    // ================= Stage 2: half0 (x) half1 across groups =============
    float* c4 = sm;            // reuse buffer set 0
    float* c3 = sm + 4096;
    float* c2 = sm + 4608;
    float* c1 = sm + 4672;

    __syncthreads();           // stage-1 reads complete before overwrite

    if (g2 == 1) {
        *(float4*)(c4 + m * 8)     = make_float4(h4[0], h4[1], h4[2], h4[3]);
        *(float4*)(c4 + m * 8 + 4) = make_float4(h4[4], h4[5], h4[6], h4[7]);
        c3[m] = h3;
        if (k == 0)        c2[m >> 3] = h2v;
        if ((m & 63) == 0) c1[i]      = h1v;
    }
    __syncthreads();

    if (g2 == 0) {
        float bb1[8];
        #pragma unroll
        for (int l = 0; l < 8; ++l) bb1[l] = c1[l];
        const float4 u0 = *(const float4*)(c2 + k * 8);
        const float4 u1 = *(const float4*)(c2 + k * 8 + 4);
        const float b2kl[8] = {u0.x,u0.y,u0.z,u0.w,u1.x,u1.y,u1.z,u1.w};
        const float b2jk = c2[j * 8 + k];
        const float4 r0 = *(const float4*)(c3 + j * 64 + k * 8);
        const float4 r1 = *(const float4*)(c3 + j * 64 + k * 8 + 4);
        const float b3jkl[8] = {r0.x,r0.y,r0.z,r0.w,r1.x,r1.y,r1.z,r1.w};
        const float4 w0 = *(const float4*)(c4 + m * 8);
        const float4 w1 = *(const float4*)(c4 + m * 8 + 4);
        const float b4m[8] = {w0.x,w0.y,w0.z,w0.w,w1.x,w1.y,w1.z,w1.w};
        const float bb3m = c3[m];

        float r4[8];
        #pragma unroll
        for (int l = 0; l < 8; ++l) {
            float acc = h4[l] + b4m[l];
            acc = fmaf(h3,  bb1[l],   acc);
            acc = fmaf(h2v, b2kl[l],  acc);
            acc = fmaf(h1v, b3jkl[l], acc);
            r4[l] = acc;
        }
        float r3 = h3 + bb3m;
        r3 = fmaf(h2v, bb1[k], r3);
        r3 = fmaf(h1v, b2jk,  r3);
        float r2 = h2v + c2[m >> 3];
        r2 = fmaf(h1v, bb1[j], r2);
        const float r1s = h1v + bb1[i];

        // ---- Emit: [s1(8) | s2(64) | s3(512) | s4(4096)] per batch.
        float* ob = out + (size_t)b * OUT_PER_B;
        float4* o4 = (float4*)(ob + DD + DD*DD + DD*DD*DD + m * 8);
        o4[0] = make_float4(r4[0], r4[1], r4[2], r4[3]);
        o4[1] = make_float4(r4[4], r4[5], r4[6], r4[7]);
        ob[DD + DD*DD + m] = r3;
        if (k == 0)        ob[DD + (m >> 3)] = r2;
        if ((m & 63) == 0) ob[m >> 6]        = r1s;
    }
}

extern "C" void kernel_launch(void* const* d_in, const int* in_sizes, int n_in,
                              void* d_out, int out_size)
{
    const float* path = (const float*)d_in[0];
    float* out = (float*)d_out;
    const int nb = in_sizes[0] / (SD * DD);   // 128
    signature_kernel<<<nb, 1024>>>(path, out);
}

// round 8
// speedup vs baseline: 1.0732x; 1.0732x over previous
#include <cuda_runtime.h>
#include <cuda_bf16.h>

// Path signature, truncation level 4.
// path: (B=128, S=512, D=8) fp32 -> out: (B, 8+64+512+4096 = 4680) fp32
//
// One CTA per batch, 512 threads; thread m owns (i,j,k)=(m>>6,(m>>3)&7,m&7).
// Two time halves run in the two lanes of f32x2 registers (R6 scheme).
// This revision software-pipelines the main loop: stream vectors are
// prefetched one sub-iteration ahead (double-buffered, role-swapped by a
// manual unroll-2 so there are no register copies), and row data is loaded
// at sub-iteration top while the dependent c-chain runs, hiding LDS latency.

#define SD 512
#define DD 8
#define HT 256                 // steps per half
#define TRP_STRIDE 516         // padded floats per d-row of transposed table
#define OUT_PER_B (DD + DD*DD + DD*DD*DD + DD*DD*DD*DD)  // 4680

typedef unsigned long long u64;

__device__ __forceinline__ u64 dup2(float x) {
    u64 r; asm("mov.b64 %0, {%1, %1};" : "=l"(r) : "f"(x)); return r;
}
__device__ __forceinline__ u64 fmul2(u64 a, u64 b) {
    u64 r; asm("mul.rn.f32x2 %0, %1, %2;" : "=l"(r) : "l"(a), "l"(b)); return r;
}
__device__ __forceinline__ u64 fadd2(u64 a, u64 b) {
    u64 r; asm("add.rn.f32x2 %0, %1, %2;" : "=l"(r) : "l"(a), "l"(b)); return r;
}
__device__ __forceinline__ u64 ffma2(u64 a, u64 b, u64 c) {
    u64 r; asm("fma.rn.f32x2 %0, %1, %2, %3;" : "=l"(r) : "l"(a), "l"(b), "l"(c)); return r;
}
__device__ __forceinline__ void facc2(u64& d, u64 a, u64 b) {
    asm("fma.rn.f32x2 %0, %1, %2, %0;" : "+l"(d) : "l"(a), "l"(b));
}
__device__ __forceinline__ float lo2(u64 a) {
    float l, h; asm("mov.b64 {%0, %1}, %2;" : "=f"(l), "=f"(h) : "l"(a)); return l;
}
__device__ __forceinline__ float hi2(u64 a) {
    float l, h; asm("mov.b64 {%0, %1}, %2;" : "=f"(l), "=f"(h) : "l"(a)); return h;
}

__global__ __launch_bounds__(512, 1)
void signature_kernel(const float* __restrict__ path, float* __restrict__ out)
{
    // [0 .. 4095]            rowp: 256 x 8 float2  {half0, half1}  (16 KB)
    // [4096 .. 4096+8*516)   trp:  8 x 256 float2, padded stride   (16.5 KB)
    __shared__ __align__(16) float sm[4096 + DD * TRP_STRIDE];

    const int b = blockIdx.x;
    const int m = threadIdx.x;            // 0..511
    const float* p = path + (size_t)b * SD * DD;

    // ---- Build pair-interleaved increment tables. Thread t computes inc[t].
    {
        const int t = m;
        float r[8];
        if (t < SD - 1) {
            const float4 a0 = *(const float4*)(p + t * DD);
            const float4 a1 = *(const float4*)(p + t * DD + 4);
            const float4 c0 = *(const float4*)(p + (t + 1) * DD);
            const float4 c1 = *(const float4*)(p + (t + 1) * DD + 4);
            r[0]=c0.x-a0.x; r[1]=c0.y-a0.y; r[2]=c0.z-a0.z; r[3]=c0.w-a0.w;
            r[4]=c1.x-a1.x; r[5]=c1.y-a1.y; r[6]=c1.z-a1.z; r[7]=c1.w-a1.w;
        } else {
            #pragma unroll
            for (int d = 0; d < 8; ++d) r[d] = 0.f;   // pad: exp(0)=identity
        }
        const int tp = t & (HT - 1);      // pair-time
        const int sl = t >> 8;            // 0 = half A (lo), 1 = half B (hi)
        #pragma unroll
        for (int l = 0; l < 8; ++l) sm[tp * 16 + l * 2 + sl] = r[l];
        #pragma unroll
        for (int d = 0; d < 8; ++d) sm[4096 + d * TRP_STRIDE + tp * 2 + sl] = r[d];
    }
    __syncthreads();

    const int i = m >> 6;
    const int j = (m >> 3) & 7;
    const int k = m & 7;

    u64 s1 = 0ull, s2 = 0ull, s3 = 0ull;
    u64 s4[8];
    #pragma unroll
    for (int l = 0; l < 8; ++l) s4[l] = 0ull;

    const u64 C24 = dup2(1.f / 24.f);
    const u64 C6  = dup2(1.f / 6.f);
    const u64 CH  = dup2(0.5f);
    const u64 C3  = dup2(3.f);

    const ulonglong2* __restrict__ rowq = (const ulonglong2*)sm;  // 4 per tp
    const float* __restrict__ pI = sm + 4096 + i * TRP_STRIDE;
    const float* __restrict__ pJ = sm + 4096 + j * TRP_STRIDE;
    const float* __restrict__ pK = sm + 4096 + k * TRP_STRIDE;

    // STEP with preloaded row data (RA..RD) and stream scalars.
#define STEPR(DI, DJ, DK, RA, RB, RC, RD) do {                                \
    const u64 h  = fmul2((DJ), (DK));                                         \
    const u64 t1 = fmul2((DI), C24);                                          \
    const u64 t2 = ffma2(s1, C6, t1);                                         \
    const u64 c0 = ffma2(h, t2, s3);                                          \
    const u64 u  = fmul2(s2, (DK));                                           \
    const u64 c  = ffma2(u, CH, c0);                                          \
    facc2(s4[0], (RA).x, c);                                                  \
    facc2(s4[1], (RA).y, c);                                                  \
    facc2(s4[2], (RB).x, c);                                                  \
    facc2(s4[3], (RB).y, c);                                                  \
    facc2(s4[4], (RC).x, c);                                                  \
    facc2(s4[5], (RC).y, c);                                                  \
    facc2(s4[6], (RD).x, c);                                                  \
    facc2(s4[7], (RD).y, c);                                                  \
    const u64 g3 = ffma2(t2, C3, t1);   /* = s1/2 + dxi/6 */                  \
    s3 = ffma2(h, g3, fadd2(s3, u));                                          \
    s2 = ffma2((DJ), ffma2((DI), CH, s1), s2);                                \
    s1 = fadd2(s1, (DI));                                                     \
} while (0)

    // Software pipeline: streams double-buffered (0/1), role-swapped by the
    // manual unroll-2; rows loaded at sub-iteration top ahead of the c-chain.
    ulonglong2 sI0 = *(const ulonglong2*)(pI);
    ulonglong2 sJ0 = *(const ulonglong2*)(pJ);
    ulonglong2 sK0 = *(const ulonglong2*)(pK);
    ulonglong2 sI1, sJ1, sK1;

    #pragma unroll 1
    for (int g = 0; g < HT / 2; g += 2) {
        // ---- sub-iteration g (uses buffer 0), prefetch buffer 1 for g+1
        {
            const ulonglong2 ra = rowq[(2 * g    ) * 4 + 0];
            const ulonglong2 rb = rowq[(2 * g    ) * 4 + 1];
            const ulonglong2 rc = rowq[(2 * g    ) * 4 + 2];
            const ulonglong2 rd = rowq[(2 * g    ) * 4 + 3];
            const ulonglong2 re = rowq[(2 * g + 1) * 4 + 0];
            const ulonglong2 rf = rowq[(2 * g + 1) * 4 + 1];
            const ulonglong2 rg = rowq[(2 * g + 1) * 4 + 2];
            const ulonglong2 rh = rowq[(2 * g + 1) * 4 + 3];
            sI1 = *(const ulonglong2*)(pI + (g + 1) * 4);   // g+1 < HT/2 always
            sJ1 = *(const ulonglong2*)(pJ + (g + 1) * 4);
            sK1 = *(const ulonglong2*)(pK + (g + 1) * 4);
            STEPR(sI0.x, sJ0.x, sK0.x, ra, rb, rc, rd);
            STEPR(sI0.y, sJ0.y, sK0.y, re, rf, rg, rh);
        }
        // ---- sub-iteration g+1 (uses buffer 1), prefetch buffer 0 for g+2
        {
            const int gn = (g + 2 < HT / 2) ? (g + 2) : 0;  // dummy reload ok
            const ulonglong2 ra = rowq[(2 * g + 2) * 4 + 0];
            const ulonglong2 rb = rowq[(2 * g + 2) * 4 + 1];
            const ulonglong2 rc = rowq[(2 * g + 2) * 4 + 2];
            const ulonglong2 rd = rowq[(2 * g + 2) * 4 + 3];
            const ulonglong2 re = rowq[(2 * g + 3) * 4 + 0];
            const ulonglong2 rf = rowq[(2 * g + 3) * 4 + 1];
            const ulonglong2 rg = rowq[(2 * g + 3) * 4 + 2];
            const ulonglong2 rh = rowq[(2 * g + 3) * 4 + 3];
            sI0 = *(const ulonglong2*)(pI + gn * 4);
            sJ0 = *(const ulonglong2*)(pJ + gn * 4);
            sK0 = *(const ulonglong2*)(pK + gn * 4);
            STEPR(sI1.x, sJ1.x, sK1.x, ra, rb, rc, rd);
            STEPR(sI1.y, sJ1.y, sK1.y, re, rf, rg, rh);
        }
    }
#undef STEPR

    // ---- Split packed state: A = lo lanes (first half), B = hi lanes.
    float a4[8], b4v[8];
    #pragma unroll
    for (int l = 0; l < 8; ++l) { a4[l] = lo2(s4[l]); b4v[l] = hi2(s4[l]); }
    const float a1 = lo2(s1), a2 = lo2(s2), a3 = lo2(s3);
    const float bb1s = hi2(s1), bb2s = hi2(s2), bb3s = hi2(s3);

    // ---- Chen combine: S = A (x) B through shared memory (aliases tables).
    float* b4 = sm;            // 4096 floats
    float* b3 = sm + 4096;     // 512
    float* b2 = sm + 4608;     // 64
    float* b1 = sm + 4672;     // 8

    __syncthreads();           // done reading increment tables

    *(float4*)(b4 + m * 8)     = make_float4(b4v[0], b4v[1], b4v[2], b4v[3]);
    *(float4*)(b4 + m * 8 + 4) = make_float4(b4v[4], b4v[5], b4v[6], b4v[7]);
    b3[m] = bb3s;
    if (k == 0)        b2[m >> 3] = bb2s;
    if ((m & 63) == 0) b1[i]      = bb1s;
    __syncthreads();

    float bb1[8];
    #pragma unroll
    for (int l = 0; l < 8; ++l) bb1[l] = b1[l];
    const float4 q0 = *(const float4*)(b2 + k * 8);
    const float4 q1 = *(const float4*)(b2 + k * 8 + 4);
    const float b2kl[8] = {q0.x,q0.y,q0.z,q0.w,q1.x,q1.y,q1.z,q1.w};
    const float b2jk = b2[j * 8 + k];
    const float4 r0 = *(const float4*)(b3 + j * 64 + k * 8);
    const float4 r1 = *(const float4*)(b3 + j * 64 + k * 8 + 4);
    const float b3jkl[8] = {r0.x,r0.y,r0.z,r0.w,r1.x,r1.y,r1.z,r1.w};
    const float4 w0 = *(const float4*)(b4 + m * 8);
    const float4 w1 = *(const float4*)(b4 + m * 8 + 4);
    const float b4m[8] = {w0.x,w0.y,w0.z,w0.w,w1.x,w1.y,w1.z,w1.w};
    const float bb3m = b3[m];

    float r4[8];
    #pragma unroll
    for (int l = 0; l < 8; ++l) {
        float acc = a4[l] + b4m[l];
        acc = fmaf(a3, bb1[l],   acc);
        acc = fmaf(a2, b2kl[l],  acc);
        acc = fmaf(a1, b3jkl[l], acc);
        r4[l] = acc;
    }
    float r3 = a3 + bb3m;
    r3 = fmaf(a2, bb1[k], r3);
    r3 = fmaf(a1, b2jk,  r3);
    float r2 = a2 + b2[m >> 3];
    r2 = fmaf(a1, bb1[j], r2);
    const float r1s = a1 + bb1[i];

    // ---- Emit: [s1(8) | s2(64) | s3(512) | s4(4096)] per batch.
    float* ob = out + (size_t)b * OUT_PER_B;
    float4* o4 = (float4*)(ob + DD + DD*DD + DD*DD*DD + m * 8);
    o4[0] = make_float4(r4[0], r4[1], r4[2], r4[3]);
    o4[1] = make_float4(r4[4], r4[5], r4[6], r4[7]);
    ob[DD + DD*DD + m] = r3;
    if (k == 0)        ob[DD + (m >> 3)] = r2;
    if ((m & 63) == 0) ob[m >> 6]        = r1s;
}

extern "C" void kernel_launch(void* const* d_in, const int* in_sizes, int n_in,
                              void* d_out, int out_size)
{
    const float* path = (const float*)d_in[0];
    float* out = (float*)d_out;
    const int nb = in_sizes[0] / (SD * DD);   // 128
    signature_kernel<<<nb, 512>>>(path, out);
}

// round 10
// speedup vs baseline: 1.1378x; 1.0602x over previous
#include <cuda_runtime.h>
#include <cuda_bf16.h>

// Path signature, truncation level 4.
// path: (B=128, S=512, D=8) fp32 -> out: (B, 8+64+512+4096 = 4680) fp32
//
// One CTA per batch, 512 threads; thread m owns (i,j,k)=(m>>6,(m>>3)&7,m&7).
// Two time halves run in the two lanes of f32x2 registers (R6 scheme):
// pair-interleaved smem tables deliver {halfA, halfB} operand pairs, the
// packed coefficient {cA,cB} feeds fma.rn.f32x2 rank-1 updates directly.
// This revision: (a) unroll 4 for a wider ptxas scheduling window,
// (b) loop-carried s1/s2/s3 updates retired BEFORE the facc2 block so the
// next iteration's dependent chain is ready while the s4 FMAs drain.

#define SD 512
#define DD 8
#define HT 256                 // steps per half
#define TRP_STRIDE 516         // padded floats per d-row of transposed table
#define OUT_PER_B (DD + DD*DD + DD*DD*DD + DD*DD*DD*DD)  // 4680

typedef unsigned long long u64;

__device__ __forceinline__ u64 dup2(float x) {
    u64 r; asm("mov.b64 %0, {%1, %1};" : "=l"(r) : "f"(x)); return r;
}
__device__ __forceinline__ u64 fmul2(u64 a, u64 b) {
    u64 r; asm("mul.rn.f32x2 %0, %1, %2;" : "=l"(r) : "l"(a), "l"(b)); return r;
}
__device__ __forceinline__ u64 fadd2(u64 a, u64 b) {
    u64 r; asm("add.rn.f32x2 %0, %1, %2;" : "=l"(r) : "l"(a), "l"(b)); return r;
}
__device__ __forceinline__ u64 ffma2(u64 a, u64 b, u64 c) {
    u64 r; asm("fma.rn.f32x2 %0, %1, %2, %3;" : "=l"(r) : "l"(a), "l"(b), "l"(c)); return r;
}
__device__ __forceinline__ void facc2(u64& d, u64 a, u64 b) {
    asm("fma.rn.f32x2 %0, %1, %2, %0;" : "+l"(d) : "l"(a), "l"(b));
}
__device__ __forceinline__ float lo2(u64 a) {
    float l, h; asm("mov.b64 {%0, %1}, %2;" : "=f"(l), "=f"(h) : "l"(a)); return l;
}
__device__ __forceinline__ float hi2(u64 a) {
    float l, h; asm("mov.b64 {%0, %1}, %2;" : "=f"(l), "=f"(h) : "l"(a)); return h;
}

__global__ __launch_bounds__(512, 1)
void signature_kernel(const float* __restrict__ path, float* __restrict__ out)
{
    // [0 .. 4095]            rowp: 256 x 8 float2  {half0, half1}  (16 KB)
    // [4096 .. 4096+8*516)   trp:  8 x 256 float2, padded stride   (16.5 KB)
    __shared__ __align__(16) float sm[4096 + DD * TRP_STRIDE];

    const int b = blockIdx.x;
    const int m = threadIdx.x;            // 0..511
    const float* p = path + (size_t)b * SD * DD;

    // ---- Build pair-interleaved increment tables. Thread t computes inc[t].
    {
        const int t = m;
        float r[8];
        if (t < SD - 1) {
            const float4 a0 = *(const float4*)(p + t * DD);
            const float4 a1 = *(const float4*)(p + t * DD + 4);
            const float4 c0 = *(const float4*)(p + (t + 1) * DD);
            const float4 c1 = *(const float4*)(p + (t + 1) * DD + 4);
            r[0]=c0.x-a0.x; r[1]=c0.y-a0.y; r[2]=c0.z-a0.z; r[3]=c0.w-a0.w;
            r[4]=c1.x-a1.x; r[5]=c1.y-a1.y; r[6]=c1.z-a1.z; r[7]=c1.w-a1.w;
        } else {
            #pragma unroll
            for (int d = 0; d < 8; ++d) r[d] = 0.f;   // pad: exp(0)=identity
        }
        const int tp = t & (HT - 1);      // pair-time
        const int sl = t >> 8;            // 0 = half A (lo), 1 = half B (hi)
        #pragma unroll
        for (int l = 0; l < 8; ++l) sm[tp * 16 + l * 2 + sl] = r[l];
        #pragma unroll
        for (int d = 0; d < 8; ++d) sm[4096 + d * TRP_STRIDE + tp * 2 + sl] = r[d];
    }
    __syncthreads();

    const int i = m >> 6;
    const int j = (m >> 3) & 7;
    const int k = m & 7;

    u64 s1 = 0ull, s2 = 0ull, s3 = 0ull;
    u64 s4[8];
    #pragma unroll
    for (int l = 0; l < 8; ++l) s4[l] = 0ull;

    const u64 C24 = dup2(1.f / 24.f);
    const u64 C6  = dup2(1.f / 6.f);
    const u64 CH  = dup2(0.5f);
    const u64 C3  = dup2(3.f);

    const float* __restrict__ rowb = sm;
    const float* __restrict__ pI = sm + 4096 + i * TRP_STRIDE;
    const float* __restrict__ pJ = sm + 4096 + j * TRP_STRIDE;
    const float* __restrict__ pK = sm + 4096 + k * TRP_STRIDE;

#define STEP(DI, DJ, DK, TP_) do {                                           \
    const ulonglong2 ra = *(const ulonglong2*)(rowb + (TP_) * 16);            \
    const ulonglong2 rb = *(const ulonglong2*)(rowb + (TP_) * 16 + 4);        \
    const ulonglong2 rc = *(const ulonglong2*)(rowb + (TP_) * 16 + 8);        \
    const ulonglong2 rd = *(const ulonglong2*)(rowb + (TP_) * 16 + 12);       \
    const u64 h  = fmul2((DJ), (DK));                                         \
    const u64 t1 = fmul2((DI), C24);                                          \
    const u64 t2 = ffma2(s1, C6, t1);                                         \
    const u64 c0 = ffma2(h, t2, s3);                                          \
    const u64 u  = fmul2(s2, (DK));                                           \
    const u64 c  = ffma2(u, CH, c0);                                          \
    /* retire loop-carried state FIRST: next step's chain becomes ready */    \
    const u64 g3 = ffma2(t2, C3, t1);   /* = s1/2 + dxi/6 */                  \
    s3 = ffma2(h, g3, fadd2(s3, u));                                          \
    s2 = ffma2((DJ), ffma2((DI), CH, s1), s2);                                \
    s1 = fadd2(s1, (DI));                                                     \
    /* then drain the rank-1 level-4 update off the packed coefficient */     \
    facc2(s4[0], ra.x, c);                                                    \
    facc2(s4[1], ra.y, c);                                                    \
    facc2(s4[2], rb.x, c);                                                    \
    facc2(s4[3], rb.y, c);                                                    \
    facc2(s4[4], rc.x, c);                                                    \
    facc2(s4[5], rc.y, c);                                                    \
    facc2(s4[6], rd.x, c);                                                    \
    facc2(s4[7], rd.y, c);                                                    \
} while (0)

    #pragma unroll 4
    for (int g = 0; g < HT / 2; ++g) {
        // one LDS.128 per stream serves two pair-steps ({t}, {t+1} float2s)
        const ulonglong2 di = *(const ulonglong2*)(pI + g * 4);
        const ulonglong2 dj = *(const ulonglong2*)(pJ + g * 4);
        const ulonglong2 dk = *(const ulonglong2*)(pK + g * 4);
        STEP(di.x, dj.x, dk.x, 2 * g);
        STEP(di.y, dj.y, dk.y, 2 * g + 1);
    }
#undef STEP

    // ---- Split packed state: A = lo lanes (first half), B = hi lanes.
    float a4[8], b4v[8];
    #pragma unroll
    for (int l = 0; l < 8; ++l) { a4[l] = lo2(s4[l]); b4v[l] = hi2(s4[l]); }
    const float a1 = lo2(s1), a2 = lo2(s2), a3 = lo2(s3);
    const float bb1s = hi2(s1), bb2s = hi2(s2), bb3s = hi2(s3);

    // ---- Chen combine: S = A (x) B through shared memory (aliases tables).
    float* b4 = sm;            // 4096 floats
    float* b3 = sm + 4096;     // 512
    float* b2 = sm + 4608;     // 64
    float* b1 = sm + 4672;     // 8

    __syncthreads();           // done reading increment tables

    *(float4*)(b4 + m * 8)     = make_float4(b4v[0], b4v[1], b4v[2], b4v[3]);
    *(float4*)(b4 + m * 8 + 4) = make_float4(b4v[4], b4v[5], b4v[6], b4v[7]);
    b3[m] = bb3s;
    if (k == 0)        b2[m >> 3] = bb2s;
    if ((m & 63) == 0) b1[i]      = bb1s;
    __syncthreads();

    float bb1[8];
    #pragma unroll
    for (int l = 0; l < 8; ++l) bb1[l] = b1[l];
    const float4 q0 = *(const float4*)(b2 + k * 8);
    const float4 q1 = *(const float4*)(b2 + k * 8 + 4);
    const float b2kl[8] = {q0.x,q0.y,q0.z,q0.w,q1.x,q1.y,q1.z,q1.w};
    const float b2jk = b2[j * 8 + k];
    const float4 r0 = *(const float4*)(b3 + j * 64 + k * 8);
    const float4 r1 = *(const float4*)(b3 + j * 64 + k * 8 + 4);
    const float b3jkl[8] = {r0.x,r0.y,r0.z,r0.w,r1.x,r1.y,r1.z,r1.w};
    const float4 w0 = *(const float4*)(b4 + m * 8);
    const float4 w1 = *(const float4*)(b4 + m * 8 + 4);
    const float b4m[8] = {w0.x,w0.y,w0.z,w0.w,w1.x,w1.y,w1.z,w1.w};
    const float bb3m = b3[m];

    float r4[8];
    #pragma unroll
    for (int l = 0; l < 8; ++l) {
        float acc = a4[l] + b4m[l];
        acc = fmaf(a3, bb1[l],   acc);
        acc = fmaf(a2, b2kl[l],  acc);
        acc = fmaf(a1, b3jkl[l], acc);
        r4[l] = acc;
    }
    float r3 = a3 + bb3m;
    r3 = fmaf(a2, bb1[k], r3);
    r3 = fmaf(a1, b2jk,  r3);
    float r2 = a2 + b2[m >> 3];
    r2 = fmaf(a1, bb1[j], r2);
    const float r1s = a1 + bb1[i];

    // ---- Emit: [s1(8) | s2(64) | s3(512) | s4(4096)] per batch.
    float* ob = out + (size_t)b * OUT_PER_B;
    float4* o4 = (float4*)(ob + DD + DD*DD + DD*DD*DD + m * 8);
    o4[0] = make_float4(r4[0], r4[1], r4[2], r4[3]);
    o4[1] = make_float4(r4[4], r4[5], r4[6], r4[7]);
    ob[DD + DD*DD + m] = r3;
    if (k == 0)        ob[DD + (m >> 3)] = r2;
    if ((m & 63) == 0) ob[m >> 6]        = r1s;
}

extern "C" void kernel_launch(void* const* d_in, const int* in_sizes, int n_in,
                              void* d_out, int out_size)
{
    const float* path = (const float*)d_in[0];
    float* out = (float*)d_out;
    const int nb = in_sizes[0] / (SD * DD);   // 128
    signature_kernel<<<nb, 512>>>(path, out);
}